// round 6
// baseline (speedup 1.0000x reference)
#include <cuda_runtime.h>
#include <cuda_fp16.h>
#include <cstdint>

// ---------------------------------------------------------------------------
// TTM recurrence, GB300 — wavefront pipeline + fp16 weight cache.
//  - softmax over singleton axis == 1  => Wq/Wk dead.
//  - wavefront stage s = i + a (34 stages): fc1/fc2 streamed once per stage,
//    dotted against up to 3 activation vectors.
//  - weights converted fp32->fp16 once per launch into __device__ scratch
//    (117 MB), streamed as fp16, accumulated in fp32: DRAM 7.6 GB -> ~3.9 GB.
// ---------------------------------------------------------------------------

#define NBLK   148
#define NTHR   512
#define NWB    16
#define NWARPS (NBLK * NWB)   // 2368
#define MDIM   2048
#define HDIM   8192
#define NAVG   32
#define NTK    3
#define NST    (NAVG + NTK - 1)   // 34

#define NWVO   (NTK * MDIM * MDIM)   // 12,582,912
#define NFC    (HDIM * MDIM)         // 16,777,216

__device__ __half g_Wv16[NWVO];
__device__ __half g_Wo16[NWVO];
__device__ __half g_fc1_16[NFC];
__device__ __half g_fc2_16[NFC];

__device__ float g_xcfT[MDIM * NAVG];
__device__ float g_s0[NAVG * MDIM];
__device__ float g_sbuf[2][NTK][MDIM];
__device__ float g_s1[NTK][MDIM];
__device__ float g_vv[NTK][MDIM];
__device__ float g_hh[NTK][HDIM];
__device__ float g_vcum[2][NTK][MDIM];
__device__ int            g_cnt;
__device__ volatile int   g_sense;

extern __shared__ float sm[];        // 96 KB dynamic

// ----------------------- fp32 -> fp16 conversion ---------------------------
__device__ __forceinline__ void conv_region(const float* __restrict__ s,
                                            __half* __restrict__ d,
                                            int n, int t0, int stride) {
    const float4* s4 = reinterpret_cast<const float4*>(s);
    uint2* d4 = reinterpret_cast<uint2*>(d);
    int n4 = n >> 2;
    for (int i = t0; i < n4; i += stride) {
        float4 v = s4[i];
        __half2 a = __floats2half2_rn(v.x, v.y);
        __half2 b = __floats2half2_rn(v.z, v.w);
        uint2 o;
        o.x = *reinterpret_cast<unsigned*>(&a);
        o.y = *reinterpret_cast<unsigned*>(&b);
        d4[i] = o;
    }
}

__global__ void __launch_bounds__(256)
conv_all(const float* __restrict__ Wv, const float* __restrict__ Wo,
         const float* __restrict__ fc1, const float* __restrict__ fc2) {
    int t0 = blockIdx.x * blockDim.x + threadIdx.x;
    int stride = gridDim.x * blockDim.x;
    conv_region(Wv,  g_Wv16,   NWVO, t0, stride);
    conv_region(Wo,  g_Wo16,   NWVO, t0, stride);
    conv_region(fc1, g_fc1_16, NFC,  t0, stride);
    conv_region(fc2, g_fc2_16, NFC,  t0, stride);
}

// --------------------------- grid barrier ----------------------------------
__device__ __forceinline__ void grid_sync(int* lsense) {
    __syncthreads();
    if (threadIdx.x == 0) {
        int s = 1 - *lsense;
        *lsense = s;
        __threadfence();
        if (atomicAdd(&g_cnt, 1) == NBLK - 1) {
            atomicExch(&g_cnt, 0);
            __threadfence();
            g_sense = s;
        } else {
            while (g_sense != s) { __nanosleep(64); }
        }
        __threadfence();
    }
    __syncthreads();
}

// --------------------------- block reduction -------------------------------
__device__ __forceinline__ float blk_sum(float v) {
    __shared__ float red[16];
    #pragma unroll
    for (int o = 16; o; o >>= 1) v += __shfl_xor_sync(0xffffffffu, v, o);
    int w = threadIdx.x >> 5, l = threadIdx.x & 31;
    if (l == 0) red[w] = v;
    __syncthreads();
    if (threadIdx.x < 32) {
        float t = (l < NWB) ? red[l] : 0.f;
        #pragma unroll
        for (int o = 8; o; o >>= 1) t += __shfl_xor_sync(0xffffffffu, t, o);
        if (l == 0) red[0] = t;
    }
    __syncthreads();
    float r = red[0];
    __syncthreads();
    return r;
}

__device__ __forceinline__ void stage_ln(const float* __restrict__ src,
                                         const float* __restrict__ gma,
                                         const float* __restrict__ bta,
                                         float* __restrict__ dst,
                                         bool addres) {
    float vals[4];
    float s = 0.f;
    #pragma unroll
    for (int k = 0; k < 4; k++) {
        vals[k] = src[threadIdx.x + k * NTHR];
        s += vals[k];
    }
    float mean = blk_sum(s) * (1.f / (float)MDIM);
    float q = 0.f;
    #pragma unroll
    for (int k = 0; k < 4; k++) {
        float d = vals[k] - mean;
        q += d * d;
    }
    float var  = blk_sum(q) * (1.f / (float)MDIM);
    float rstd = rsqrtf(var + 1e-5f);
    #pragma unroll
    for (int k = 0; k < 4; k++) {
        int m = threadIdx.x + k * NTHR;
        float xn = (vals[k] - mean) * rstd * gma[m] + bta[m];
        dst[m] = addres ? (xn + vals[k]) : xn;
    }
    __syncthreads();
}

// Batched warp dot: fp16 weight row vs NACT fp32 smem vectors, fp32 accum.
template <int NELEM, int NACT>
__device__ __forceinline__ void warp_dotN_h(const __half* __restrict__ w,
                                            const float* __restrict__ xs,
                                            int xs4, int lane,
                                            float* __restrict__ res) {
    const uint4*  w8 = reinterpret_cast<const uint4*>(w);   // 8 halves each
    const float4* x4 = reinterpret_cast<const float4*>(xs);
    float accA[NACT], accB[NACT];
    #pragma unroll
    for (int k = 0; k < NACT; k++) { accA[k] = 0.f; accB[k] = 0.f; }
    #pragma unroll 4
    for (int j = 0; j < NELEM / 512; j++) {
        int base = lane + j * 64;
        uint4 wa = w8[base];
        uint4 wb = w8[base + 32];
        float2 a0 = __half22float2(*reinterpret_cast<const __half2*>(&wa.x));
        float2 a1 = __half22float2(*reinterpret_cast<const __half2*>(&wa.y));
        float2 a2 = __half22float2(*reinterpret_cast<const __half2*>(&wa.z));
        float2 a3 = __half22float2(*reinterpret_cast<const __half2*>(&wa.w));
        float2 b0 = __half22float2(*reinterpret_cast<const __half2*>(&wb.x));
        float2 b1 = __half22float2(*reinterpret_cast<const __half2*>(&wb.y));
        float2 b2 = __half22float2(*reinterpret_cast<const __half2*>(&wb.z));
        float2 b3 = __half22float2(*reinterpret_cast<const __half2*>(&wb.w));
        #pragma unroll
        for (int k = 0; k < NACT; k++) {
            const float4* xk = x4 + k * xs4;
            float4 xa0 = xk[2 * base];
            float4 xa1 = xk[2 * base + 1];
            float4 xb0 = xk[2 * base + 64];
            float4 xb1 = xk[2 * base + 65];
            accA[k] += a0.x * xa0.x + a0.y * xa0.y + a1.x * xa0.z + a1.y * xa0.w
                     + a2.x * xa1.x + a2.y * xa1.y + a3.x * xa1.z + a3.y * xa1.w;
            accB[k] += b0.x * xb0.x + b0.y * xb0.y + b1.x * xb0.z + b1.y * xb0.w
                     + b2.x * xb1.x + b2.y * xb1.y + b3.x * xb1.z + b3.y * xb1.w;
        }
    }
    #pragma unroll
    for (int k = 0; k < NACT; k++) {
        float a = accA[k] + accB[k];
        #pragma unroll
        for (int o = 16; o; o >>= 1) a += __shfl_xor_sync(0xffffffffu, a, o);
        res[k] = a;
    }
}

__global__ void __launch_bounds__(NTHR, 1)
ttm_persistent(const float* __restrict__ x,
               const float* __restrict__ weight,
               const float* __restrict__ ln1_g, const float* __restrict__ ln1_b,
               const float* __restrict__ ln2_g, const float* __restrict__ ln2_b,
               const float* __restrict__ fc1_b, const float* __restrict__ fc2_b,
               float* __restrict__ out) {
    const int tid  = threadIdx.x;
    const int lane = tid & 31;
    const int wid  = tid >> 5;
    const int gw   = blockIdx.x * NWB + wid;
    int lsense = 0;

    for (int g = blockIdx.x * NTHR + tid; g < 2 * NTK * MDIM; g += NBLK * NTHR)
        (&g_vcum[0][0][0])[g] = 0.f;

    // ---- Phase A: segment-average x -> xcfT[m][i] ----
    for (int g = blockIdx.x * NTHR + tid; g < NAVG * MDIM; g += NBLK * NTHR) {
        int i = g & 31;
        int b = (g >> 5) & 127;
        int a = g >> 12;
        const float* p = x + (size_t)a * (128 * 512) + (size_t)b * 512 + i * 16;
        float ssum = 0.f;
        #pragma unroll
        for (int k = 0; k < 16; k++) ssum += p[k];
        g_xcfT[(b * 16 + a) * 32 + i] = ssum * (1.f / 16.f);
    }
    grid_sync(&lsense);   // barrier 1

    // ---- Phase B: s0 (fp32) ----
    {
        const int  row = gw;
        const bool has = row < MDIM;
        float acc[32];
        #pragma unroll
        for (int ii = 0; ii < 32; ii++) acc[ii] = 0.f;
        for (int c = 0; c < 8; c++) {
            for (int idx = tid; idx < 8192; idx += NTHR) {
                int mm = idx >> 5, ii = idx & 31;
                sm[mm * 33 + ii] = g_xcfT[(c * 256 + mm) * 32 + ii];
            }
            __syncthreads();
            if (has) {
                const float* wr = weight + (size_t)row * MDIM + c * 256;
                for (int mm = lane; mm < 256; mm += 32) {
                    float w = wr[mm];
                    #pragma unroll
                    for (int ii = 0; ii < 32; ii++)
                        acc[ii] = fmaf(w, sm[mm * 33 + ii], acc[ii]);
                }
            }
            __syncthreads();
        }
        if (has) {
            float myval = 0.f;
            #pragma unroll
            for (int ii = 0; ii < 32; ii++) {
                float v = acc[ii];
                #pragma unroll
                for (int o = 16; o; o >>= 1) v += __shfl_xor_sync(0xffffffffu, v, o);
                if (lane == ii) myval = v;
            }
            int   t    = row >> 1;
            float freq = expf(-(float)t * (4.f / 2048.f) * 9.210340371976184f);
            float ang  = (float)lane * freq;
            float bias = (row & 1) ? cosf(ang) : sinf(ang);
            g_s0[(size_t)lane * MDIM + row] = myval + bias;
        }
    }
    grid_sync(&lsense);   // barrier 2

    // ---- wavefront: 34 stages x 4 barriers ----
    for (int st = 0; st < NST; st++) {
        const int p = st & 1, q = p ^ 1;
        int act_a[3], act_i[3], nact = 0;
        #pragma unroll
        for (int a = 0; a < NTK; a++) {
            int i = st - a;
            if (i >= 0 && i < NAVG) { act_a[nact] = a; act_i[nact] = i; nact++; }
        }
        const int nrows = nact * MDIM;

        // P0: xn_k = LN1(s_in_k); v_k = Wv[a_k] @ xn_k
        for (int k = 0; k < nact; k++) {
            const float* src = (act_a[k] == 0) ? (g_s0 + (size_t)act_i[k] * MDIM)
                                               : g_sbuf[p][act_a[k]];
            stage_ln(src, ln1_g, ln1_b, sm + k * MDIM, false);
        }
        for (int t = gw; t < nrows; t += NWARPS) {
            int k = t >> 11, r = t & (MDIM - 1);
            const __half* W = g_Wv16 + ((size_t)act_a[k] * MDIM + r) * MDIM;
            float res[1];
            warp_dotN_h<2048, 1>(W, sm + k * MDIM, 512, lane, res);
            if (lane == 0) g_vv[k][r] = res[0];
        }
        grid_sync(&lsense);

        // P1: u_k = vcum + v (smem); s1_k = Wo[a_k] @ u_k + s_in_k
        for (int k = 0; k < nact; k++) {
            const float* vc = g_vcum[p][act_a[k]];
            for (int m = tid; m < MDIM; m += NTHR)
                sm[k * MDIM + m] = vc[m] + g_vv[k][m];
        }
        __syncthreads();
        if (blockIdx.x < NTK) {
            int a = blockIdx.x, kf = -1;
            for (int k = 0; k < nact; k++) if (act_a[k] == a) kf = k;
            if (kf >= 0)
                for (int m = tid; m < MDIM; m += NTHR)
                    g_vcum[q][a][m] = sm[kf * MDIM + m];
            else
                for (int m = tid; m < MDIM; m += NTHR)
                    g_vcum[q][a][m] = g_vcum[p][a][m];
        }
        for (int t = gw; t < nrows; t += NWARPS) {
            int k = t >> 11, r = t & (MDIM - 1);
            const __half* W = g_Wo16 + ((size_t)act_a[k] * MDIM + r) * MDIM;
            float res[1];
            warp_dotN_h<2048, 1>(W, sm + k * MDIM, 512, lane, res);
            if (lane == 0) {
                float sin_r = (act_a[k] == 0) ? g_s0[(size_t)act_i[k] * MDIM + r]
                                              : g_sbuf[p][act_a[k]][r];
                g_s1[k][r] = res[0] + sin_r;
            }
        }
        grid_sync(&lsense);

        // P2: s2_k = LN2(s1_k)+s1_k; h_k = gelu(fc1 @ s2_k + b1)
        for (int k = 0; k < nact; k++)
            stage_ln(g_s1[k], ln2_g, ln2_b, sm + k * MDIM, true);
        if (nact == 3) {
            for (int r = gw; r < HDIM; r += NWARPS) {
                float res[3];
                warp_dotN_h<2048, 3>(g_fc1_16 + (size_t)r * MDIM, sm, 512, lane, res);
                if (lane == 0) {
                    float b = fc1_b[r];
                    #pragma unroll
                    for (int k = 0; k < 3; k++) {
                        float xv = res[k] + b;
                        g_hh[k][r] = 0.5f * xv * (1.f + erff(xv * 0.7071067811865476f));
                    }
                }
            }
        } else if (nact == 2) {
            for (int r = gw; r < HDIM; r += NWARPS) {
                float res[2];
                warp_dotN_h<2048, 2>(g_fc1_16 + (size_t)r * MDIM, sm, 512, lane, res);
                if (lane == 0) {
                    float b = fc1_b[r];
                    #pragma unroll
                    for (int k = 0; k < 2; k++) {
                        float xv = res[k] + b;
                        g_hh[k][r] = 0.5f * xv * (1.f + erff(xv * 0.7071067811865476f));
                    }
                }
            }
        } else {
            for (int r = gw; r < HDIM; r += NWARPS) {
                float res[1];
                warp_dotN_h<2048, 1>(g_fc1_16 + (size_t)r * MDIM, sm, 512, lane, res);
                if (lane == 0) {
                    float xv = res[0] + fc1_b[r];
                    g_hh[0][r] = 0.5f * xv * (1.f + erff(xv * 0.7071067811865476f));
                }
            }
        }
        grid_sync(&lsense);

        // P3: stage h_k (96KB smem); s_out_k = fc2 @ h_k + b2
        for (int idx = tid; idx < nact * HDIM; idx += NTHR)
            sm[idx] = (&g_hh[0][0])[idx];
        __syncthreads();
        if (gw < MDIM) {
            const int r = gw;
            const __half* W = g_fc2_16 + (size_t)r * HDIM;
            float res[3];
            if (nact == 3)      warp_dotN_h<8192, 3>(W, sm, 2048, lane, res);
            else if (nact == 2) warp_dotN_h<8192, 2>(W, sm, 2048, lane, res);
            else                warp_dotN_h<8192, 1>(W, sm, 2048, lane, res);
            if (lane == 0) {
                float b = fc2_b[r];
                for (int k = 0; k < nact; k++) {
                    float val = res[k] + b;
                    int a = act_a[k], i = act_i[k];
                    if (a == NTK - 1) out[(size_t)i * MDIM + r] = val;
                    else              g_sbuf[q][a + 1][r] = val;
                }
            }
        }
        grid_sync(&lsense);
    }
    // barriers: 2 + 34*4 = 138 (EVEN) -> barrier state self-resets.
}

extern "C" void kernel_launch(void* const* d_in, const int* in_sizes, int n_in,
                              void* d_out, int out_size) {
    (void)in_sizes; (void)n_in; (void)out_size;
    const float* x      = (const float*)d_in[0];
    const float* weight = (const float*)d_in[1];
    // d_in[2]=Wq, d_in[3]=Wk : dead (softmax over scalar == 1)
    const float* Wv     = (const float*)d_in[4];
    const float* Wo     = (const float*)d_in[5];
    const float* ln1_g  = (const float*)d_in[6];
    const float* ln1_b  = (const float*)d_in[7];
    const float* ln2_g  = (const float*)d_in[8];
    const float* ln2_b  = (const float*)d_in[9];
    const float* fc1_w  = (const float*)d_in[10];
    const float* fc1_b  = (const float*)d_in[11];
    const float* fc2_w  = (const float*)d_in[12];
    const float* fc2_b  = (const float*)d_in[13];

    conv_all<<<NBLK * 8, 256>>>(Wv, Wo, fc1_w, fc2_w);

    const int smem_bytes = NTK * HDIM * sizeof(float);   // 96 KB
    cudaFuncSetAttribute(ttm_persistent,
                         cudaFuncAttributeMaxDynamicSharedMemorySize, smem_bytes);
    ttm_persistent<<<NBLK, NTHR, smem_bytes>>>(x, weight,
                                               ln1_g, ln1_b, ln2_g, ln2_b,
                                               fc1_b, fc2_b,
                                               (float*)d_out);
}

// round 11
// speedup vs baseline: 1.1089x; 1.1089x over previous
#include <cuda_runtime.h>
#include <cuda_fp16.h>
#include <cstdint>

// ---------------------------------------------------------------------------
// TTM recurrence, GB300 — wavefront + fp16 weights, 2 blocks/SM occupancy.
// R6 result: fp16 halved DRAM bytes but dur regressed -> latency-bound.
// This round: keep the R6-proven 512-thread block body; raise occupancy via
// NBLK=296 + __launch_bounds__(512,2)  (64 regs/thr, 2x96KB smem per SM).
// Minimal deltas vs R6: lean warp dot (fits 64-reg cap), fc2 half-row split.
// ---------------------------------------------------------------------------

#define NBLK   296
#define NTHR   512
#define NWB    16
#define NWARPS (NBLK * NWB)   // 4736
#define MDIM   2048
#define HDIM   8192
#define NAVG   32
#define NTK    3
#define NST    (NAVG + NTK - 1)   // 34

#define NWVO   (NTK * MDIM * MDIM)
#define NFC    (HDIM * MDIM)

__device__ __half g_Wv16[NWVO];
__device__ __half g_Wo16[NWVO];
__device__ __half g_fc1_16[NFC];
__device__ __half g_fc2_16[NFC];

__device__ float g_xcfT[MDIM * NAVG];
__device__ float g_s0[NAVG * MDIM];
__device__ float g_sbuf[2][NTK][MDIM];
__device__ float g_s1[NTK][MDIM];
__device__ float g_vv[NTK][MDIM];
__device__ float g_hh[NTK][HDIM];
__device__ float g_vcum[2][NTK][MDIM];
__device__ int            g_cnt;
__device__ volatile int   g_sense;

extern __shared__ float sm[];        // 96 KB dynamic

// ----------------------- fp32 -> fp16 conversion ---------------------------
__device__ __forceinline__ void conv_region(const float* __restrict__ s,
                                            __half* __restrict__ d,
                                            int n, int t0, int stride) {
    const float4* s4 = reinterpret_cast<const float4*>(s);
    uint2* d4 = reinterpret_cast<uint2*>(d);
    int n4 = n >> 2;
    for (int i = t0; i < n4; i += stride) {
        float4 v = s4[i];
        __half2 a = __floats2half2_rn(v.x, v.y);
        __half2 b = __floats2half2_rn(v.z, v.w);
        uint2 o;
        o.x = *reinterpret_cast<unsigned*>(&a);
        o.y = *reinterpret_cast<unsigned*>(&b);
        d4[i] = o;
    }
}

__global__ void __launch_bounds__(256)
conv_all(const float* __restrict__ Wv, const float* __restrict__ Wo,
         const float* __restrict__ fc1, const float* __restrict__ fc2) {
    int t0 = blockIdx.x * blockDim.x + threadIdx.x;
    int stride = gridDim.x * blockDim.x;
    conv_region(Wv,  g_Wv16,   NWVO, t0, stride);
    conv_region(Wo,  g_Wo16,   NWVO, t0, stride);
    conv_region(fc1, g_fc1_16, NFC,  t0, stride);
    conv_region(fc2, g_fc2_16, NFC,  t0, stride);
}

// --------------------------- grid barrier ----------------------------------
__device__ __forceinline__ void grid_sync(int* lsense) {
    __syncthreads();
    if (threadIdx.x == 0) {
        int s = 1 - *lsense;
        *lsense = s;
        __threadfence();
        if (atomicAdd(&g_cnt, 1) == NBLK - 1) {
            atomicExch(&g_cnt, 0);
            __threadfence();
            g_sense = s;
        } else {
            while (g_sense != s) { __nanosleep(64); }
        }
        __threadfence();
    }
    __syncthreads();
}

// --------------------------- block reduction (16 warps, R6-proven) ---------
__device__ __forceinline__ float blk_sum(float v) {
    __shared__ float red[16];
    #pragma unroll
    for (int o = 16; o; o >>= 1) v += __shfl_xor_sync(0xffffffffu, v, o);
    int w = threadIdx.x >> 5, l = threadIdx.x & 31;
    if (l == 0) red[w] = v;
    __syncthreads();
    if (threadIdx.x < 32) {
        float t = (l < NWB) ? red[l] : 0.f;
        #pragma unroll
        for (int o = 8; o; o >>= 1) t += __shfl_xor_sync(0xffffffffu, t, o);
        if (l == 0) red[0] = t;
    }
    __syncthreads();
    float r = red[0];
    __syncthreads();
    return r;
}

// R6-proven stage_ln (512 threads, 4 vals/thread).
__device__ __forceinline__ void stage_ln(const float* __restrict__ src,
                                         const float* __restrict__ gma,
                                         const float* __restrict__ bta,
                                         float* __restrict__ dst,
                                         bool addres) {
    float vals[4];
    float s = 0.f;
    #pragma unroll
    for (int k = 0; k < 4; k++) {
        vals[k] = src[threadIdx.x + k * NTHR];
        s += vals[k];
    }
    float mean = blk_sum(s) * (1.f / (float)MDIM);
    float q = 0.f;
    #pragma unroll
    for (int k = 0; k < 4; k++) {
        float d = vals[k] - mean;
        q += d * d;
    }
    float var  = blk_sum(q) * (1.f / (float)MDIM);
    float rstd = rsqrtf(var + 1e-5f);
    #pragma unroll
    for (int k = 0; k < 4; k++) {
        int m = threadIdx.x + k * NTHR;
        float xn = (vals[k] - mean) * rstd * gma[m] + bta[m];
        dst[m] = addres ? (xn + vals[k]) : xn;
    }
    __syncthreads();
}

// Lean warp dot: fp16 row (NELEM elems) vs NACT fp32 smem vectors.
// 1 uint4 (8 halves) per lane per iter — fits the 64-reg budget.
template <int NELEM, int NACT>
__device__ __forceinline__ void warp_dotN_h(const __half* __restrict__ w,
                                            const float* __restrict__ xs,
                                            int xs4, int lane,
                                            float* __restrict__ res) {
    const uint4*  w8 = reinterpret_cast<const uint4*>(w);
    const float4* x4 = reinterpret_cast<const float4*>(xs);
    float acc[NACT];
    #pragma unroll
    for (int k = 0; k < NACT; k++) acc[k] = 0.f;
    #pragma unroll 2
    for (int j = 0; j < NELEM / 256; j++) {
        int base = lane + j * 32;
        uint4 wa = w8[base];
        float2 a0 = __half22float2(*reinterpret_cast<const __half2*>(&wa.x));
        float2 a1 = __half22float2(*reinterpret_cast<const __half2*>(&wa.y));
        float2 a2 = __half22float2(*reinterpret_cast<const __half2*>(&wa.z));
        float2 a3 = __half22float2(*reinterpret_cast<const __half2*>(&wa.w));
        #pragma unroll
        for (int k = 0; k < NACT; k++) {
            const float4* xk = x4 + k * xs4;
            float4 xa = xk[2 * base];
            float4 xb = xk[2 * base + 1];
            acc[k] += (a0.x * xa.x + a0.y * xa.y) + (a1.x * xa.z + a1.y * xa.w)
                    + (a2.x * xb.x + a2.y * xb.y) + (a3.x * xb.z + a3.y * xb.w);
        }
    }
    #pragma unroll
    for (int k = 0; k < NACT; k++) {
        float a = acc[k];
        #pragma unroll
        for (int o = 16; o; o >>= 1) a += __shfl_xor_sync(0xffffffffu, a, o);
        res[k] = a;
    }
}

__global__ void __launch_bounds__(NTHR, 2)
ttm_persistent(const float* __restrict__ x,
               const float* __restrict__ weight,
               const float* __restrict__ ln1_g, const float* __restrict__ ln1_b,
               const float* __restrict__ ln2_g, const float* __restrict__ ln2_b,
               const float* __restrict__ fc1_b, const float* __restrict__ fc2_b,
               float* __restrict__ out) {
    __shared__ float s_part[NWB][3];    // fc2 half-row partials
    const int tid  = threadIdx.x;
    const int lane = tid & 31;
    const int wid  = tid >> 5;
    const int gw   = blockIdx.x * NWB + wid;
    int lsense = 0;

    for (int g = blockIdx.x * NTHR + tid; g < 2 * NTK * MDIM; g += NBLK * NTHR)
        (&g_vcum[0][0][0])[g] = 0.f;

    // ---- Phase A: segment-average x -> xcfT[m][i] ----
    for (int g = blockIdx.x * NTHR + tid; g < NAVG * MDIM; g += NBLK * NTHR) {
        int i = g & 31;
        int b = (g >> 5) & 127;
        int a = g >> 12;
        const float* p = x + (size_t)a * (128 * 512) + (size_t)b * 512 + i * 16;
        float ssum = 0.f;
        #pragma unroll
        for (int k = 0; k < 16; k++) ssum += p[k];
        g_xcfT[(b * 16 + a) * 32 + i] = ssum * (1.f / 16.f);
    }
    grid_sync(&lsense);   // barrier 1

    // ---- Phase B: s0 (fp32), R6-proven layout (acc[32] may spill; one-time)
    {
        const int  row = gw;
        const bool has = row < MDIM;
        float acc[32];
        #pragma unroll
        for (int ii = 0; ii < 32; ii++) acc[ii] = 0.f;
        for (int c = 0; c < 8; c++) {
            for (int idx = tid; idx < 8192; idx += NTHR) {
                int mm = idx >> 5, ii = idx & 31;
                sm[mm * 33 + ii] = g_xcfT[(c * 256 + mm) * 32 + ii];
            }
            __syncthreads();
            if (has) {
                const float* wr = weight + (size_t)row * MDIM + c * 256;
                for (int mm = lane; mm < 256; mm += 32) {
                    float w = wr[mm];
                    #pragma unroll
                    for (int ii = 0; ii < 32; ii++)
                        acc[ii] = fmaf(w, sm[mm * 33 + ii], acc[ii]);
                }
            }
            __syncthreads();
        }
        if (has) {
            float myval = 0.f;
            #pragma unroll
            for (int ii = 0; ii < 32; ii++) {
                float v = acc[ii];
                #pragma unroll
                for (int o = 16; o; o >>= 1) v += __shfl_xor_sync(0xffffffffu, v, o);
                if (lane == ii) myval = v;
            }
            int   t    = row >> 1;
            float freq = expf(-(float)t * (4.f / 2048.f) * 9.210340371976184f);
            float ang  = (float)lane * freq;
            float bias = (row & 1) ? cosf(ang) : sinf(ang);
            g_s0[(size_t)lane * MDIM + row] = myval + bias;
        }
    }
    grid_sync(&lsense);   // barrier 2

    // ---- wavefront: 34 stages x 4 barriers ----
    for (int st = 0; st < NST; st++) {
        const int p = st & 1, q = p ^ 1;
        int act_a[3], act_i[3], nact = 0;
        #pragma unroll
        for (int a = 0; a < NTK; a++) {
            int i = st - a;
            if (i >= 0 && i < NAVG) { act_a[nact] = a; act_i[nact] = i; nact++; }
        }
        const int nrows = nact * MDIM;

        // P0: xn_k = LN1(s_in_k); v_k = Wv[a_k] @ xn_k
        for (int k = 0; k < nact; k++) {
            const float* src = (act_a[k] == 0) ? (g_s0 + (size_t)act_i[k] * MDIM)
                                               : g_sbuf[p][act_a[k]];
            stage_ln(src, ln1_g, ln1_b, sm + k * MDIM, false);
        }
        for (int t = gw; t < nrows; t += NWARPS) {
            int k = t >> 11, r = t & (MDIM - 1);
            const __half* W = g_Wv16 + ((size_t)act_a[k] * MDIM + r) * MDIM;
            float res[1];
            warp_dotN_h<2048, 1>(W, sm + k * MDIM, 512, lane, res);
            if (lane == 0) g_vv[k][r] = res[0];
        }
        grid_sync(&lsense);

        // P1: u_k = vcum + v (smem); s1_k = Wo[a_k] @ u_k + s_in_k
        for (int k = 0; k < nact; k++) {
            const float* vc = g_vcum[p][act_a[k]];
            for (int m = tid; m < MDIM; m += NTHR)
                sm[k * MDIM + m] = vc[m] + g_vv[k][m];
        }
        __syncthreads();
        if (blockIdx.x < NTK) {
            int a = blockIdx.x, kf = -1;
            for (int k = 0; k < nact; k++) if (act_a[k] == a) kf = k;
            if (kf >= 0)
                for (int m = tid; m < MDIM; m += NTHR)
                    g_vcum[q][a][m] = sm[kf * MDIM + m];
            else
                for (int m = tid; m < MDIM; m += NTHR)
                    g_vcum[q][a][m] = g_vcum[p][a][m];
        }
        for (int t = gw; t < nrows; t += NWARPS) {
            int k = t >> 11, r = t & (MDIM - 1);
            const __half* W = g_Wo16 + ((size_t)act_a[k] * MDIM + r) * MDIM;
            float res[1];
            warp_dotN_h<2048, 1>(W, sm + k * MDIM, 512, lane, res);
            if (lane == 0) {
                float sin_r = (act_a[k] == 0) ? g_s0[(size_t)act_i[k] * MDIM + r]
                                              : g_sbuf[p][act_a[k]][r];
                g_s1[k][r] = res[0] + sin_r;
            }
        }
        grid_sync(&lsense);

        // P2: s2_k = LN2(s1_k)+s1_k; h_k = gelu(fc1 @ s2_k + b1)
        for (int k = 0; k < nact; k++)
            stage_ln(g_s1[k], ln2_g, ln2_b, sm + k * MDIM, true);
        if (nact == 3) {
            for (int r = gw; r < HDIM; r += NWARPS) {
                float res[3];
                warp_dotN_h<2048, 3>(g_fc1_16 + (size_t)r * MDIM, sm, 512, lane, res);
                if (lane == 0) {
                    float b = fc1_b[r];
                    #pragma unroll
                    for (int k = 0; k < 3; k++) {
                        float xv = res[k] + b;
                        g_hh[k][r] = 0.5f * xv * (1.f + erff(xv * 0.7071067811865476f));
                    }
                }
            }
        } else if (nact == 2) {
            for (int r = gw; r < HDIM; r += NWARPS) {
                float res[2];
                warp_dotN_h<2048, 2>(g_fc1_16 + (size_t)r * MDIM, sm, 512, lane, res);
                if (lane == 0) {
                    float b = fc1_b[r];
                    #pragma unroll
                    for (int k = 0; k < 2; k++) {
                        float xv = res[k] + b;
                        g_hh[k][r] = 0.5f * xv * (1.f + erff(xv * 0.7071067811865476f));
                    }
                }
            }
        } else {
            for (int r = gw; r < HDIM; r += NWARPS) {
                float res[1];
                warp_dotN_h<2048, 1>(g_fc1_16 + (size_t)r * MDIM, sm, 512, lane, res);
                if (lane == 0) {
                    float xv = res[0] + fc1_b[r];
                    g_hh[0][r] = 0.5f * xv * (1.f + erff(xv * 0.7071067811865476f));
                }
            }
        }
        grid_sync(&lsense);

        // P3: stage h_k; fc2 rows split into 2 half-dots, warp-pair combine.
        for (int idx = tid; idx < nact * HDIM; idx += NTHR)
            sm[idx] = (&g_hh[0][0])[idx];
        __syncthreads();
        {
            const int t = gw;                 // 4096 half-row tasks
            if (t < 2 * MDIM) {
                int r = t >> 1, half = t & 1;
                const __half* W = g_fc2_16 + (size_t)r * HDIM + half * 4096;
                const float*  X = sm + half * 4096;
                float res[3];
                if (nact == 3)      warp_dotN_h<4096, 3>(W, X, 2048, lane, res);
                else if (nact == 2) warp_dotN_h<4096, 2>(W, X, 2048, lane, res);
                else                warp_dotN_h<4096, 1>(W, X, 2048, lane, res);
                if (lane == 0)
                    for (int k = 0; k < nact; k++) s_part[wid][k] = res[k];
            }
            __syncthreads();
            if ((wid & 1) == 0 && t < 2 * MDIM && lane == 0) {
                int r = t >> 1;
                float b = fc2_b[r];
                for (int k = 0; k < nact; k++) {
                    float val = s_part[wid][k] + s_part[wid + 1][k] + b;
                    int a = act_a[k], i = act_i[k];
                    if (a == NTK - 1) out[(size_t)i * MDIM + r] = val;
                    else              g_sbuf[q][a + 1][r] = val;
                }
            }
        }
        grid_sync(&lsense);
    }
    // barriers: 2 + 34*4 = 138 (EVEN) -> barrier state self-resets.
}

extern "C" void kernel_launch(void* const* d_in, const int* in_sizes, int n_in,
                              void* d_out, int out_size) {
    (void)in_sizes; (void)n_in; (void)out_size;
    const float* x      = (const float*)d_in[0];
    const float* weight = (const float*)d_in[1];
    // d_in[2]=Wq, d_in[3]=Wk : dead (softmax over scalar == 1)
    const float* Wv     = (const float*)d_in[4];
    const float* Wo     = (const float*)d_in[5];
    const float* ln1_g  = (const float*)d_in[6];
    const float* ln1_b  = (const float*)d_in[7];
    const float* ln2_g  = (const float*)d_in[8];
    const float* ln2_b  = (const float*)d_in[9];
    const float* fc1_w  = (const float*)d_in[10];
    const float* fc1_b  = (const float*)d_in[11];
    const float* fc2_w  = (const float*)d_in[12];
    const float* fc2_b  = (const float*)d_in[13];

    conv_all<<<NBLK * 4, 256>>>(Wv, Wo, fc1_w, fc2_w);

    const int smem_bytes = NTK * HDIM * sizeof(float);   // 96 KB
    cudaFuncSetAttribute(ttm_persistent,
                         cudaFuncAttributeMaxDynamicSharedMemorySize, smem_bytes);
    ttm_persistent<<<NBLK, NTHR, smem_bytes>>>(x, weight,
                                               ln1_g, ln1_b, ln2_g, ln2_b,
                                               fc1_b, fc2_b,
                                               (float*)d_out);
}

// round 16
// speedup vs baseline: 1.3789x; 1.2435x over previous
#include <cuda_runtime.h>
#include <cuda_fp16.h>
#include <cstdint>

// ---------------------------------------------------------------------------
// TTM recurrence, GB300 — wavefront + fp16 weights + 2blk/SM + 2-ROW TILING.
// R11: occ 25->49% gave only 1.11x; L1 (smem) = 49% is the hot pipe.
// Fix: each warp-task = 2 consecutive weight rows sharing x smem loads
//      (LDS bytes -50%), and every phase becomes ONE balanced pass:
//      Wv/Wo 3072 tasks, fc1 4096, fc2 1024 row-pairs x 4 quarter-cols
//      combined by aligned 4-warp groups via smem.
// ---------------------------------------------------------------------------

#define NBLK   296
#define NTHR   512
#define NWB    16
#define NWARPS (NBLK * NWB)   // 4736
#define MDIM   2048
#define HDIM   8192
#define NAVG   32
#define NTK    3
#define NST    (NAVG + NTK - 1)   // 34

#define NWVO   (NTK * MDIM * MDIM)
#define NFC    (HDIM * MDIM)

__device__ __half g_Wv16[NWVO];
__device__ __half g_Wo16[NWVO];
__device__ __half g_fc1_16[NFC];
__device__ __half g_fc2_16[NFC];

__device__ float g_xcfT[MDIM * NAVG];
__device__ float g_s0[NAVG * MDIM];
__device__ float g_sbuf[2][NTK][MDIM];
__device__ float g_s1[NTK][MDIM];
__device__ float g_vv[NTK][MDIM];
__device__ float g_hh[NTK][HDIM];
__device__ float g_vcum[2][NTK][MDIM];
__device__ int            g_cnt;
__device__ volatile int   g_sense;

extern __shared__ float sm[];        // 96 KB dynamic

// ----------------------- fp32 -> fp16 conversion ---------------------------
__device__ __forceinline__ void conv_region(const float* __restrict__ s,
                                            __half* __restrict__ d,
                                            int n, int t0, int stride) {
    const float4* s4 = reinterpret_cast<const float4*>(s);
    uint2* d4 = reinterpret_cast<uint2*>(d);
    int n4 = n >> 2;
    for (int i = t0; i < n4; i += stride) {
        float4 v = s4[i];
        __half2 a = __floats2half2_rn(v.x, v.y);
        __half2 b = __floats2half2_rn(v.z, v.w);
        uint2 o;
        o.x = *reinterpret_cast<unsigned*>(&a);
        o.y = *reinterpret_cast<unsigned*>(&b);
        d4[i] = o;
    }
}

__global__ void __launch_bounds__(256)
conv_all(const float* __restrict__ Wv, const float* __restrict__ Wo,
         const float* __restrict__ fc1, const float* __restrict__ fc2) {
    int t0 = blockIdx.x * blockDim.x + threadIdx.x;
    int stride = gridDim.x * blockDim.x;
    conv_region(Wv,  g_Wv16,   NWVO, t0, stride);
    conv_region(Wo,  g_Wo16,   NWVO, t0, stride);
    conv_region(fc1, g_fc1_16, NFC,  t0, stride);
    conv_region(fc2, g_fc2_16, NFC,  t0, stride);
}

// --------------------------- grid barrier ----------------------------------
__device__ __forceinline__ void grid_sync(int* lsense) {
    __syncthreads();
    if (threadIdx.x == 0) {
        int s = 1 - *lsense;
        *lsense = s;
        __threadfence();
        if (atomicAdd(&g_cnt, 1) == NBLK - 1) {
            atomicExch(&g_cnt, 0);
            __threadfence();
            g_sense = s;
        } else {
            while (g_sense != s) { __nanosleep(64); }
        }
        __threadfence();
    }
    __syncthreads();
}

// --------------------------- block reduction -------------------------------
__device__ __forceinline__ float blk_sum(float v) {
    __shared__ float red[16];
    #pragma unroll
    for (int o = 16; o; o >>= 1) v += __shfl_xor_sync(0xffffffffu, v, o);
    int w = threadIdx.x >> 5, l = threadIdx.x & 31;
    if (l == 0) red[w] = v;
    __syncthreads();
    if (threadIdx.x < 32) {
        float t = (l < NWB) ? red[l] : 0.f;
        #pragma unroll
        for (int o = 8; o; o >>= 1) t += __shfl_xor_sync(0xffffffffu, t, o);
        if (l == 0) red[0] = t;
    }
    __syncthreads();
    float r = red[0];
    __syncthreads();
    return r;
}

__device__ __forceinline__ void stage_ln(const float* __restrict__ src,
                                         const float* __restrict__ gma,
                                         const float* __restrict__ bta,
                                         float* __restrict__ dst,
                                         bool addres) {
    float vals[4];
    float s = 0.f;
    #pragma unroll
    for (int k = 0; k < 4; k++) {
        vals[k] = src[threadIdx.x + k * NTHR];
        s += vals[k];
    }
    float mean = blk_sum(s) * (1.f / (float)MDIM);
    float q = 0.f;
    #pragma unroll
    for (int k = 0; k < 4; k++) {
        float d = vals[k] - mean;
        q += d * d;
    }
    float var  = blk_sum(q) * (1.f / (float)MDIM);
    float rstd = rsqrtf(var + 1e-5f);
    #pragma unroll
    for (int k = 0; k < 4; k++) {
        int m = threadIdx.x + k * NTHR;
        float xn = (vals[k] - mean) * rstd * gma[m] + bta[m];
        dst[m] = addres ? (xn + vals[k]) : xn;
    }
    __syncthreads();
}

// 2-row warp dot: two fp16 rows (NELEM elems each) vs NACT fp32 smem vectors.
// x float4 loads are shared across both rows (halves LDS traffic).
template <int NELEM, int NACT>
__device__ __forceinline__ void warp_dot2_h(const __half* __restrict__ wA,
                                            const __half* __restrict__ wB,
                                            const float* __restrict__ xs,
                                            int xs4, int lane,
                                            float* __restrict__ resA,
                                            float* __restrict__ resB) {
    const uint4*  wa8 = reinterpret_cast<const uint4*>(wA);
    const uint4*  wb8 = reinterpret_cast<const uint4*>(wB);
    const float4* x4  = reinterpret_cast<const float4*>(xs);
    float accA[NACT], accB[NACT];
    #pragma unroll
    for (int k = 0; k < NACT; k++) { accA[k] = 0.f; accB[k] = 0.f; }
    #pragma unroll 2
    for (int j = 0; j < NELEM / 256; j++) {
        int base = lane + j * 32;
        uint4 wa = wa8[base];
        uint4 wb = wb8[base];
        float2 a0 = __half22float2(*reinterpret_cast<const __half2*>(&wa.x));
        float2 a1 = __half22float2(*reinterpret_cast<const __half2*>(&wa.y));
        float2 a2 = __half22float2(*reinterpret_cast<const __half2*>(&wa.z));
        float2 a3 = __half22float2(*reinterpret_cast<const __half2*>(&wa.w));
        float2 b0 = __half22float2(*reinterpret_cast<const __half2*>(&wb.x));
        float2 b1 = __half22float2(*reinterpret_cast<const __half2*>(&wb.y));
        float2 b2 = __half22float2(*reinterpret_cast<const __half2*>(&wb.z));
        float2 b3 = __half22float2(*reinterpret_cast<const __half2*>(&wb.w));
        #pragma unroll
        for (int k = 0; k < NACT; k++) {
            const float4* xk = x4 + k * xs4;
            float4 xa = xk[2 * base];
            float4 xb = xk[2 * base + 1];
            accA[k] += (a0.x * xa.x + a0.y * xa.y) + (a1.x * xa.z + a1.y * xa.w)
                     + (a2.x * xb.x + a2.y * xb.y) + (a3.x * xb.z + a3.y * xb.w);
            accB[k] += (b0.x * xa.x + b0.y * xa.y) + (b1.x * xa.z + b1.y * xa.w)
                     + (b2.x * xb.x + b2.y * xb.y) + (b3.x * xb.z + b3.y * xb.w);
        }
    }
    #pragma unroll
    for (int k = 0; k < NACT; k++) {
        float a = accA[k], b = accB[k];
        #pragma unroll
        for (int o = 16; o; o >>= 1) a += __shfl_xor_sync(0xffffffffu, a, o);
        #pragma unroll
        for (int o = 16; o; o >>= 1) b += __shfl_xor_sync(0xffffffffu, b, o);
        resA[k] = a; resB[k] = b;
    }
}

__device__ __forceinline__ float gelu_f(float xv) {
    return 0.5f * xv * (1.f + erff(xv * 0.7071067811865476f));
}

__global__ void __launch_bounds__(NTHR, 2)
ttm_persistent(const float* __restrict__ x,
               const float* __restrict__ weight,
               const float* __restrict__ ln1_g, const float* __restrict__ ln1_b,
               const float* __restrict__ ln2_g, const float* __restrict__ ln2_b,
               const float* __restrict__ fc1_b, const float* __restrict__ fc2_b,
               float* __restrict__ out) {
    __shared__ float s_part[NWB][6];    // fc2 quarter partials (2 rows x 3)
    const int tid  = threadIdx.x;
    const int lane = tid & 31;
    const int wid  = tid >> 5;
    const int gw   = blockIdx.x * NWB + wid;
    int lsense = 0;

    for (int g = blockIdx.x * NTHR + tid; g < 2 * NTK * MDIM; g += NBLK * NTHR)
        (&g_vcum[0][0][0])[g] = 0.f;

    // ---- Phase A: segment-average x -> xcfT[m][i] ----
    for (int g = blockIdx.x * NTHR + tid; g < NAVG * MDIM; g += NBLK * NTHR) {
        int i = g & 31;
        int b = (g >> 5) & 127;
        int a = g >> 12;
        const float* p = x + (size_t)a * (128 * 512) + (size_t)b * 512 + i * 16;
        float ssum = 0.f;
        #pragma unroll
        for (int k = 0; k < 16; k++) ssum += p[k];
        g_xcfT[(b * 16 + a) * 32 + i] = ssum * (1.f / 16.f);
    }
    grid_sync(&lsense);   // barrier 1

    // ---- Phase B: s0 (fp32, one-time) ----
    {
        const int  row = gw;
        const bool has = row < MDIM;
        float acc[32];
        #pragma unroll
        for (int ii = 0; ii < 32; ii++) acc[ii] = 0.f;
        for (int c = 0; c < 8; c++) {
            for (int idx = tid; idx < 8192; idx += NTHR) {
                int mm = idx >> 5, ii = idx & 31;
                sm[mm * 33 + ii] = g_xcfT[(c * 256 + mm) * 32 + ii];
            }
            __syncthreads();
            if (has) {
                const float* wr = weight + (size_t)row * MDIM + c * 256;
                for (int mm = lane; mm < 256; mm += 32) {
                    float w = wr[mm];
                    #pragma unroll
                    for (int ii = 0; ii < 32; ii++)
                        acc[ii] = fmaf(w, sm[mm * 33 + ii], acc[ii]);
                }
            }
            __syncthreads();
        }
        if (has) {
            float myval = 0.f;
            #pragma unroll
            for (int ii = 0; ii < 32; ii++) {
                float v = acc[ii];
                #pragma unroll
                for (int o = 16; o; o >>= 1) v += __shfl_xor_sync(0xffffffffu, v, o);
                if (lane == ii) myval = v;
            }
            int   t    = row >> 1;
            float freq = expf(-(float)t * (4.f / 2048.f) * 9.210340371976184f);
            float ang  = (float)lane * freq;
            float bias = (row & 1) ? cosf(ang) : sinf(ang);
            g_s0[(size_t)lane * MDIM + row] = myval + bias;
        }
    }
    grid_sync(&lsense);   // barrier 2

    // ---- wavefront: 34 stages x 4 barriers ----
    for (int st = 0; st < NST; st++) {
        const int p = st & 1, q = p ^ 1;
        int act_a[3], act_i[3], nact = 0;
        #pragma unroll
        for (int a = 0; a < NTK; a++) {
            int i = st - a;
            if (i >= 0 && i < NAVG) { act_a[nact] = a; act_i[nact] = i; nact++; }
        }

        // P0: xn_k = LN1(s_in_k); v_k = Wv[a_k] @ xn_k  (row-pair tasks)
        for (int k = 0; k < nact; k++) {
            const float* src = (act_a[k] == 0) ? (g_s0 + (size_t)act_i[k] * MDIM)
                                               : g_sbuf[p][act_a[k]];
            stage_ln(src, ln1_g, ln1_b, sm + k * MDIM, false);
        }
        for (int t = gw; t < nact * (MDIM / 2); t += NWARPS) {
            int k = t >> 10, r0 = (t & (MDIM / 2 - 1)) * 2;
            const __half* W = g_Wv16 + ((size_t)act_a[k] * MDIM + r0) * MDIM;
            float rA[1], rB[1];
            warp_dot2_h<2048, 1>(W, W + MDIM, sm + k * MDIM, 512, lane, rA, rB);
            if (lane == 0) { g_vv[k][r0] = rA[0]; g_vv[k][r0 + 1] = rB[0]; }
        }
        grid_sync(&lsense);

        // P1: u_k = vcum + v (smem); s1_k = Wo[a_k] @ u_k + s_in_k
        for (int k = 0; k < nact; k++) {
            const float* vc = g_vcum[p][act_a[k]];
            for (int m = tid; m < MDIM; m += NTHR)
                sm[k * MDIM + m] = vc[m] + g_vv[k][m];
        }
        __syncthreads();
        if (blockIdx.x < NTK) {
            int a = blockIdx.x, kf = -1;
            for (int k = 0; k < nact; k++) if (act_a[k] == a) kf = k;
            if (kf >= 0)
                for (int m = tid; m < MDIM; m += NTHR)
                    g_vcum[q][a][m] = sm[kf * MDIM + m];
            else
                for (int m = tid; m < MDIM; m += NTHR)
                    g_vcum[q][a][m] = g_vcum[p][a][m];
        }
        for (int t = gw; t < nact * (MDIM / 2); t += NWARPS) {
            int k = t >> 10, r0 = (t & (MDIM / 2 - 1)) * 2;
            const __half* W = g_Wo16 + ((size_t)act_a[k] * MDIM + r0) * MDIM;
            float rA[1], rB[1];
            warp_dot2_h<2048, 1>(W, W + MDIM, sm + k * MDIM, 512, lane, rA, rB);
            if (lane == 0) {
                const float* sin_src = (act_a[k] == 0)
                    ? (g_s0 + (size_t)act_i[k] * MDIM) : g_sbuf[p][act_a[k]];
                g_s1[k][r0]     = rA[0] + sin_src[r0];
                g_s1[k][r0 + 1] = rB[0] + sin_src[r0 + 1];
            }
        }
        grid_sync(&lsense);

        // P2: s2_k = LN2(s1_k)+s1_k; h_k = gelu(fc1 @ s2_k + b1) (row pairs)
        for (int k = 0; k < nact; k++)
            stage_ln(g_s1[k], ln2_g, ln2_b, sm + k * MDIM, true);
        for (int t = gw; t < HDIM / 2; t += NWARPS) {
            int r0 = t * 2;
            const __half* W = g_fc1_16 + (size_t)r0 * MDIM;
            float rA[3], rB[3];
            if (nact == 3)      warp_dot2_h<2048, 3>(W, W + MDIM, sm, 512, lane, rA, rB);
            else if (nact == 2) warp_dot2_h<2048, 2>(W, W + MDIM, sm, 512, lane, rA, rB);
            else                warp_dot2_h<2048, 1>(W, W + MDIM, sm, 512, lane, rA, rB);
            if (lane == 0) {
                float b0 = fc1_b[r0], b1 = fc1_b[r0 + 1];
                for (int k = 0; k < nact; k++) {
                    g_hh[k][r0]     = gelu_f(rA[k] + b0);
                    g_hh[k][r0 + 1] = gelu_f(rB[k] + b1);
                }
            }
        }
        grid_sync(&lsense);

        // P3: stage h_k; fc2 = 1024 row-pairs x 4 quarter-columns;
        //     aligned 4-warp groups combine via smem.
        for (int idx = tid; idx < nact * HDIM; idx += NTHR)
            sm[idx] = (&g_hh[0][0])[idx];
        __syncthreads();
        {
            const int t = gw;                 // 4096 tasks (u=t>>2, qd=t&3)
            if (t < 4 * (MDIM / 2)) {
                int u = t >> 2, qd = t & 3;
                int r0 = u * 2;
                const __half* W = g_fc2_16 + (size_t)r0 * HDIM + qd * 2048;
                const float*  X = sm + qd * 2048;
                float rA[3], rB[3];
                if (nact == 3)      warp_dot2_h<2048, 3>(W, W + HDIM, X, 2048, lane, rA, rB);
                else if (nact == 2) warp_dot2_h<2048, 2>(W, W + HDIM, X, 2048, lane, rA, rB);
                else                warp_dot2_h<2048, 1>(W, W + HDIM, X, 2048, lane, rA, rB);
                if (lane == 0)
                    for (int k = 0; k < nact; k++) {
                        s_part[wid][k]     = rA[k];
                        s_part[wid][3 + k] = rB[k];
                    }
            }
            __syncthreads();
            if (t < 4 * (MDIM / 2) && (wid & 3) == 0 && lane == 0) {
                int u = t >> 2, r0 = u * 2;
                float b0 = fc2_b[r0], b1 = fc2_b[r0 + 1];
                for (int k = 0; k < nact; k++) {
                    float vA = s_part[wid][k]     + s_part[wid + 1][k]
                             + s_part[wid + 2][k] + s_part[wid + 3][k] + b0;
                    float vB = s_part[wid][3 + k]     + s_part[wid + 1][3 + k]
                             + s_part[wid + 2][3 + k] + s_part[wid + 3][3 + k] + b1;
                    int a = act_a[k], i = act_i[k];
                    if (a == NTK - 1) {
                        out[(size_t)i * MDIM + r0]     = vA;
                        out[(size_t)i * MDIM + r0 + 1] = vB;
                    } else {
                        g_sbuf[q][a + 1][r0]     = vA;
                        g_sbuf[q][a + 1][r0 + 1] = vB;
                    }
                }
            }
        }
        grid_sync(&lsense);
    }
    // barriers: 2 + 34*4 = 138 (EVEN) -> barrier state self-resets.
}

extern "C" void kernel_launch(void* const* d_in, const int* in_sizes, int n_in,
                              void* d_out, int out_size) {
    (void)in_sizes; (void)n_in; (void)out_size;
    const float* x      = (const float*)d_in[0];
    const float* weight = (const float*)d_in[1];
    // d_in[2]=Wq, d_in[3]=Wk : dead (softmax over scalar == 1)
    const float* Wv     = (const float*)d_in[4];
    const float* Wo     = (const float*)d_in[5];
    const float* ln1_g  = (const float*)d_in[6];
    const float* ln1_b  = (const float*)d_in[7];
    const float* ln2_g  = (const float*)d_in[8];
    const float* ln2_b  = (const float*)d_in[9];
    const float* fc1_w  = (const float*)d_in[10];
    const float* fc1_b  = (const float*)d_in[11];
    const float* fc2_w  = (const float*)d_in[12];
    const float* fc2_b  = (const float*)d_in[13];

    conv_all<<<NBLK * 4, 256>>>(Wv, Wo, fc1_w, fc2_w);

    const int smem_bytes = NTK * HDIM * sizeof(float);   // 96 KB
    cudaFuncSetAttribute(ttm_persistent,
                         cudaFuncAttributeMaxDynamicSharedMemorySize, smem_bytes);
    ttm_persistent<<<NBLK, NTHR, smem_bytes>>>(x, weight,
                                               ln1_g, ln1_b, ln2_g, ln2_b,
                                               fc1_b, fc2_b,
                                               (float*)d_out);
}